// round 12
// baseline (speedup 1.0000x reference)
#include <cuda_runtime.h>
#include <cuda_bf16.h>
#include <cstdint>

#define DEV_INLINE __device__ __forceinline__

constexpr int B  = 64;
constexpr int C  = 2048;
constexpr int P  = 196;
constexpr int PP = 224;    // p padded: 4 warps * 56
constexpr int KK = 512;
constexpr int HS = 1024;

// ---- scratch ----
static __device__ float g_ic[B * C];
static __device__ float g_bcu[B * KK];
static __device__ float g_bsu[B * KK];
static __device__ float g_ac[B * C];     // holds exp(sc); normalized by g_den downstream
static __device__ float g_den[B];
static __device__ __nv_bfloat16 g_wsb[KK * C];               // ws in bf16
static __device__ __nv_bfloat16 g_xwb[(size_t)B * PP * C];   // weighted features bf16 [b][p][c]
static __device__ float g_ssq[B * PP];
static __device__ float g_ss[B * P];
static __device__ float g_asp[B * P];

DEV_INLINE float tanh_fast(float x) { float y; asm("tanh.approx.f32 %0, %1;" : "=f"(y) : "f"(x)); return y; }
DEV_INLINE uint32_t smem_u32(const void* p) {
    uint32_t a;
    asm("{ .reg .u64 t; cvta.to.shared.u64 t, %1; cvt.u32.u64 %0, t; }" : "=r"(a) : "l"(p));
    return a;
}
DEV_INLINE void cp16(uint32_t dst, const void* src) {
    asm volatile("cp.async.cg.shared.global [%0], [%1], 16;" :: "r"(dst), "l"(src));
}

// ---- K0: zero accumulators (bcu/bsu no longer need zeroing: k2 stores) ----
__global__ void k0_zero() {
    int i = blockIdx.x * 256 + threadIdx.x;
    if (i < B * PP) g_ssq[i] = 0.f;
    if (i < B * P)  g_ss[i]  = 0.f;
    if (i < B)      g_den[i] = 0.f;
}

// ---- Kp: ws -> bf16 ----
__global__ void kprep(const float* __restrict__ ws) {
    int i = blockIdx.x * 256 + threadIdx.x;
    if (i >= KK * C / 4) return;
    float4 v = ((const float4*)ws)[i];
    ushort4 o;
    o.x = __bfloat16_as_ushort(__float2bfloat16_rn(v.x));
    o.y = __bfloat16_as_ushort(__float2bfloat16_rn(v.y));
    o.z = __bfloat16_as_ushort(__float2bfloat16_rn(v.z));
    o.w = __bfloat16_as_ushort(__float2bfloat16_rn(v.w));
    ((ushort4*)g_wsb)[i] = o;
}

// ---- K1: per-(b,c) sum & sumsq over P ----
__global__ void k1_stats(const float* __restrict__ x) {
    int warp = (blockIdx.x * blockDim.x + threadIdx.x) >> 5;
    int lane = threadIdx.x & 31;
    if (warp >= B * C) return;
    const float4* row = (const float4*)(x + (size_t)warp * P);
    float s = 0.f, sq = 0.f;
    for (int v = lane; v < 49; v += 32) {
        float4 f = row[v];
        s  += f.x + f.y + f.z + f.w;
        sq += f.x * f.x + f.y * f.y + f.z * f.z + f.w * f.w;
    }
    #pragma unroll
    for (int o = 16; o; o >>= 1) {
        s  += __shfl_down_sync(0xffffffffu, s,  o);
        sq += __shfl_down_sync(0xffffffffu, sq, o);
    }
    if (lane == 0) g_ic[warp] = s / (196.f * fmaxf(sqrtf(sq), 1e-12f));
}

// ---- K2: full-K double-buffered proj GEMM (32 blocks, no atomics) ----
// grid (16 jt, 2 mat); block 256. Out[b][j] = W[j]·h[b] for j in [j0,j0+32), all 64 b.
constexpr int K2_SH  = 64 * 17 * 16;   // 17408
constexpr int K2_STG = K2_SH + 32 * 17 * 16;   // 26112
constexpr int SMEM_K2 = 2 * K2_STG;    // 52224

__global__ void __launch_bounds__(256) k2_gemm(const float* __restrict__ h,
                                               const float* __restrict__ whc,
                                               const float* __restrict__ whs) {
    extern __shared__ __align__(16) char sm2[];
    int jt = blockIdx.x, mat = blockIdx.y;
    const float* wsrc = mat ? whs : whc;
    float* outp = mat ? g_bsu : g_bcu;
    int j0 = jt * 32;
    int tid = threadIdx.x;
    uint32_t sb = smem_u32(sm2);

    auto load_stage = [&](int ks, int buf) {
        uint32_t hb = sb + buf * K2_STG;
        uint32_t wb = hb + K2_SH;
        const float* hs = h + ks * 64;
        const float* wsp = wsrc + (size_t)j0 * HS + ks * 64;
        #pragma unroll
        for (int r = 0; r < 4; r++) {                     // h: 64 rows x 16 f4
            int idx = tid + 256 * r;
            int row = idx >> 4, q = idx & 15;
            cp16(hb + (row * 17 + q) * 16, hs + (size_t)row * HS + q * 4);
        }
        #pragma unroll
        for (int r = 0; r < 2; r++) {                     // w: 32 rows x 16 f4
            int idx = tid + 256 * r;
            int row = idx >> 4, q = idx & 15;
            cp16(wb + (row * 17 + q) * 16, wsp + (size_t)row * HS + q * 4);
        }
        asm volatile("cp.async.commit_group;");
    };

    int bq = tid & 15, jq = tid >> 4;
    float acc[2][4] = {{0.f,0.f,0.f,0.f},{0.f,0.f,0.f,0.f}};

    load_stage(0, 0);
    for (int ks = 0; ks < 16; ks++) {
        int buf = ks & 1;
        if (ks + 1 < 16) {
            load_stage(ks + 1, buf ^ 1);
            asm volatile("cp.async.wait_group %0;" :: "n"(1));
        } else {
            asm volatile("cp.async.wait_group %0;" :: "n"(0));
        }
        __syncthreads();
        const float4* shh = (const float4*)(sm2 + buf * K2_STG);
        const float4* sww = (const float4*)(sm2 + buf * K2_STG + K2_SH);
        #pragma unroll
        for (int q = 0; q < 16; q++) {
            float4 w0 = sww[(2 * jq) * 17 + q], w1 = sww[(2 * jq + 1) * 17 + q];
            #pragma unroll
            for (int bb = 0; bb < 4; bb++) {
                float4 hv = shh[(4 * bq + bb) * 17 + q];
                acc[0][bb] = fmaf(w0.x, hv.x, fmaf(w0.y, hv.y, fmaf(w0.z, hv.z, fmaf(w0.w, hv.w, acc[0][bb]))));
                acc[1][bb] = fmaf(w1.x, hv.x, fmaf(w1.y, hv.y, fmaf(w1.z, hv.z, fmaf(w1.w, hv.w, acc[1][bb]))));
            }
        }
        __syncthreads();
    }
    #pragma unroll
    for (int jj = 0; jj < 2; jj++)
        #pragma unroll
        for (int bb = 0; bb < 4; bb++)
            outp[(4 * bq + bb) * KK + j0 + 2 * jq + jj] = acc[jj][bb];
}

// ---- K3: channel logits -> exp (no max shift; bounded), denominator atomic ----
__global__ void k3_sc(const float* __restrict__ wc, const float* __restrict__ wci,
                      const float* __restrict__ bc) {
    int b = blockIdx.y;
    int c = blockIdx.x * 256 + threadIdx.x;
    int t = threadIdx.x;
    __shared__ float swc[KK], swi[KK], sbu[KK];
    __shared__ float red[256];
    for (int i = t; i < KK; i += 256) {
        swc[i] = wc[i]; swi[i] = wci[i]; sbu[i] = g_bcu[b * KK + i] + bc[i];
    }
    __syncthreads();
    float icv = g_ic[b * C + c], acc = 0.f;
    #pragma unroll 8
    for (int j = 0; j < KK; j++)
        acc = fmaf(swi[j], tanh_fast(fmaf(swc[j], icv, sbu[j])), acc);
    float e = __expf(acc);
    g_ac[b * C + c] = e;
    red[t] = e; __syncthreads();
    for (int o = 128; o; o >>= 1) { if (t < o) red[t] += red[t + o]; __syncthreads(); }
    if (t == 0) atomicAdd(&g_den[b], red[0]);
}

// ---- K5: xwb[b][p][c] = bf16(x * exp_ac/den); ssq via serial smem column sums ----
__global__ void __launch_bounds__(256) k5_xwT(const float* __restrict__ x) {
    int b = blockIdx.y, c0 = blockIdx.x * 32;
    __shared__ float t[32][201];
    int tid = threadIdx.x;
    float invden = __fdividef(1.f, g_den[b]);
    {
        int cc = tid >> 3, q0 = tid & 7;
        float a = g_ac[b * C + c0 + cc] * invden;
        const float4* src = (const float4*)(x + ((size_t)b * C + c0 + cc) * P);
        #pragma unroll
        for (int i = 0; i < 7; i++) {
            int q = q0 + 8 * i;
            if (q < 49) {
                float4 v = src[q];
                t[cc][4 * q + 0] = v.x * a;
                t[cc][4 * q + 1] = v.y * a;
                t[cc][4 * q + 2] = v.z * a;
                t[cc][4 * q + 3] = v.w * a;
            }
        }
    }
    __syncthreads();
    int lane = tid & 31, w = tid >> 5;
    for (int p = w; p < P; p += 8)
        g_xwb[((size_t)b * PP + p) * C + c0 + lane] = __float2bfloat16_rn(t[lane][p]);
    if (tid < P) {
        float s = 0.f;
        #pragma unroll
        for (int cc = 0; cc < 32; cc++) { float v = t[cc][tid]; s = fmaf(v, v, s); }
        atomicAdd(&g_ssq[b * PP + tid], s);
    }
}

// ============ K7: bf16 mma.sync m16n8k16, M128 x N224, K-chunks of 64 ============
constexpr int A_SZ  = 128 * 144;            // 18432
constexpr int STG   = A_SZ + 224 * 144;     // 50688
constexpr int SMEM_K7 = 2 * STG + 448 * 4;  // 103168

DEV_INLINE void mma16(float* c, const uint32_t* a, const uint32_t* bf) {
    asm volatile(
        "mma.sync.aligned.m16n8k16.row.col.f32.bf16.bf16.f32 "
        "{%0,%1,%2,%3}, {%4,%5,%6,%7}, {%8,%9}, {%0,%1,%2,%3};"
        : "+f"(c[0]), "+f"(c[1]), "+f"(c[2]), "+f"(c[3])
        : "r"(a[0]), "r"(a[1]), "r"(a[2]), "r"(a[3]), "r"(bf[0]), "r"(bf[1]));
}

__global__ void __launch_bounds__(256, 1) k7_mma(const float* __restrict__ wsi,
                                                 const float* __restrict__ bs) {
    extern __shared__ __align__(16) char sm[];
    const int tid = threadIdx.x;
    const int jbase = blockIdx.x * 128;
    const int b = blockIdx.y;
    const uint32_t sb = smem_u32(sm);

    const int wid = tid >> 5, lane = tid & 31;
    const int g = lane >> 2, t4 = lane & 3;
    const int m0 = (wid & 1) * 64;
    const int n0 = (wid >> 1) * 56;

    const size_t bbase = (size_t)b * PP;

    auto load_chunk = [&](int ch, int buf) {
        uint32_t abase = sb + buf * STG;
        uint32_t bbs   = abase + A_SZ;
        const __nv_bfloat16* asrc = g_wsb + ch * 64;
        const __nv_bfloat16* bsrc = g_xwb + bbase * 2048 + ch * 64;
        int idx = tid;
        #pragma unroll
        for (int r = 0; r < 4; r++, idx += 256) {
            int row = idx >> 3, q = idx & 7;
            cp16(abase + row * 144 + q * 16, asrc + (size_t)(jbase + row) * 2048 + q * 8);
        }
        idx = tid;
        #pragma unroll
        for (int r = 0; r < 7; r++, idx += 256) {
            int row = idx >> 3, q = idx & 7;
            cp16(bbs + row * 144 + q * 16, bsrc + (size_t)row * 2048 + q * 8);
        }
        asm volatile("cp.async.commit_group;");
    };

    float acc[4][7][4];
    #pragma unroll
    for (int mf = 0; mf < 4; mf++)
        #pragma unroll
        for (int nf = 0; nf < 7; nf++)
            #pragma unroll
            for (int i = 0; i < 4; i++) acc[mf][nf][i] = 0.f;

    load_chunk(0, 0);

    for (int ch = 0; ch < 32; ch++) {
        int buf = ch & 1;
        if (ch + 1 < 32) {
            load_chunk(ch + 1, buf ^ 1);
            asm volatile("cp.async.wait_group %0;" :: "n"(1));
        } else {
            asm volatile("cp.async.wait_group %0;" :: "n"(0));
        }
        __syncthreads();

        const char* aB = sm + buf * STG + (m0 + g) * 144 + t4 * 4;
        const char* bB = sm + buf * STG + A_SZ + (n0 + g) * 144 + t4 * 4;

        #pragma unroll
        for (int kk = 0; kk < 4; kk++) {
            const int ko = kk * 32;
            uint32_t a[4][4];
            #pragma unroll
            for (int mf = 0; mf < 4; mf++) {
                const char* ap = aB + mf * 16 * 144 + ko;
                a[mf][0] = *(const uint32_t*)(ap);
                a[mf][1] = *(const uint32_t*)(ap + 8 * 144);
                a[mf][2] = *(const uint32_t*)(ap + 16);
                a[mf][3] = *(const uint32_t*)(ap + 8 * 144 + 16);
            }
            uint32_t bf[7][2];
            #pragma unroll
            for (int nf = 0; nf < 7; nf++) {
                const char* bp = bB + nf * 8 * 144 + ko;
                bf[nf][0] = *(const uint32_t*)(bp);
                bf[nf][1] = *(const uint32_t*)(bp + 16);
            }
            #pragma unroll
            for (int mf = 0; mf < 4; mf++)
                #pragma unroll
                for (int nf = 0; nf < 7; nf++)
                    mma16(acc[mf][nf], a[mf], bf[nf]);
        }
        __syncthreads();
    }

    // ---- fused epilogue (inv norms inline from ssq) ----
    float* sinv  = (float*)(sm + 2 * STG);
    float* ssacc = sinv + 224;
    for (int i = tid; i < 224; i += 256) {
        sinv[i] = 1.f / fmaxf(sqrtf(g_ssq[bbase + i]), 1e-12f);
        ssacc[i] = 0.f;
    }
    __syncthreads();

    float invp[14];
    #pragma unroll
    for (int nf = 0; nf < 7; nf++) {
        invp[nf * 2 + 0] = sinv[n0 + nf * 8 + 2 * t4 + 0];
        invp[nf * 2 + 1] = sinv[n0 + nf * 8 + 2 * t4 + 1];
    }
    float psum[14];
    #pragma unroll
    for (int i = 0; i < 14; i++) psum[i] = 0.f;

    #pragma unroll
    for (int mf = 0; mf < 4; mf++) {
        #pragma unroll
        for (int rr = 0; rr < 2; rr++) {
            int j = jbase + m0 + mf * 16 + rr * 8 + g;
            float bj = g_bsu[b * KK + j] + bs[j];
            float wj = wsi[j];
            #pragma unroll
            for (int nf = 0; nf < 7; nf++) {
                #pragma unroll
                for (int cc = 0; cc < 2; cc++) {
                    float d = acc[mf][nf][rr * 2 + cc];
                    psum[nf * 2 + cc] = fmaf(wj, tanh_fast(fmaf(d, invp[nf * 2 + cc], bj)),
                                             psum[nf * 2 + cc]);
                }
            }
        }
    }
    #pragma unroll
    for (int nf = 0; nf < 7; nf++)
        #pragma unroll
        for (int cc = 0; cc < 2; cc++) {
            int p = n0 + nf * 8 + 2 * t4 + cc;
            if (p < P) atomicAdd(&ssacc[p], psum[nf * 2 + cc]);
        }
    __syncthreads();
    if (tid < P) atomicAdd(&g_ss[b * P + tid], ssacc[tid]);
}

// ---- K8: softmax over P ----
__global__ void k8_softmax_p() {
    int b = blockIdx.x, t = threadIdx.x;
    __shared__ float red[256];
    float v = (t < P) ? g_ss[b * P + t] : -1e30f;
    red[t] = v; __syncthreads();
    for (int o = 128; o; o >>= 1) { if (t < o) red[t] = fmaxf(red[t], red[t + o]); __syncthreads(); }
    float m = red[0]; __syncthreads();
    float e = (t < P) ? __expf(v - m) : 0.f;
    red[t] = e; __syncthreads();
    for (int o = 128; o; o >>= 1) { if (t < o) red[t] += red[t + o]; __syncthreads(); }
    if (t < P) g_asp[b * P + t] = e / red[0];
}

// ---- K9: out = img * (exp_ac/den) * asp ----
__global__ void k9_out(const float* __restrict__ x, float* __restrict__ out) {
    int idx = blockIdx.x * 256 + threadIdx.x;
    if (idx >= B * C * 49) return;
    int q = idx % 49;
    int bc = idx / 49;
    int b = bc >> 11;
    float a = g_ac[bc] * __fdividef(1.f, g_den[b]);
    float4 v = ((const float4*)x)[idx];
    float4 s = ((const float4*)g_asp)[b * 49 + q];
    float4 o;
    o.x = v.x * a * s.x; o.y = v.y * a * s.y; o.z = v.z * a * s.z; o.w = v.w * a * s.w;
    ((float4*)out)[idx] = o;
}

extern "C" void kernel_launch(void* const* d_in, const int* in_sizes, int n_in,
                              void* d_out, int out_size) {
    const float* img = (const float*)d_in[0];
    const float* h   = (const float*)d_in[1];
    const float* wc  = (const float*)d_in[2];
    const float* bc  = (const float*)d_in[3];
    const float* whc = (const float*)d_in[4];
    const float* wci = (const float*)d_in[5];
    const float* ws  = (const float*)d_in[7];
    const float* bs  = (const float*)d_in[8];
    const float* whs = (const float*)d_in[9];
    const float* wsi = (const float*)d_in[10];
    float* out = (float*)d_out;

    cudaFuncSetAttribute(k7_mma, cudaFuncAttributeMaxDynamicSharedMemorySize, SMEM_K7);
    cudaFuncSetAttribute(k2_gemm, cudaFuncAttributeMaxDynamicSharedMemorySize, SMEM_K2);

    k0_zero<<<(B * PP + 255) / 256, 256>>>();
    kprep<<<(KK * C / 4 + 255) / 256, 256>>>(ws);
    k1_stats<<<(B * C) / 8, 256>>>(img);
    k2_gemm<<<dim3(16, 2), 256, SMEM_K2>>>(h, whc, whs);
    k3_sc<<<dim3(C / 256, B), 256>>>(wc, wci, bc);
    k5_xwT<<<dim3(C / 32, B), 256>>>(img);
    k7_mma<<<dim3(4, B), 256, SMEM_K7>>>(wsi, bs);
    k8_softmax_p<<<B, 256>>>();
    k9_out<<<(B * C * 49 + 255) / 256, 256>>>(img, out);
}

// round 13
// speedup vs baseline: 1.2064x; 1.2064x over previous
#include <cuda_runtime.h>
#include <cuda_bf16.h>
#include <cstdint>

#define DEV_INLINE __device__ __forceinline__

constexpr int B  = 64;
constexpr int C  = 2048;
constexpr int P  = 196;
constexpr int PP = 224;    // p padded: 4 warps * 56
constexpr int KK = 512;
constexpr int HS = 1024;

// ---- scratch ----
static __device__ float g_ic[B * C];
static __device__ float g_bcu[B * KK];
static __device__ float g_bsu[B * KK];
static __device__ float g_ac[B * C];     // exp(sc); normalized by g_den downstream
static __device__ float g_den[B];
static __device__ __nv_bfloat16 g_wsb[KK * C];               // ws in bf16
static __device__ __nv_bfloat16 g_xwb[(size_t)B * PP * C];   // weighted features bf16 [b][p][c]
static __device__ float g_ssq[B * PP];
static __device__ float g_ss[B * P];
static __device__ float g_asp[B * P];

DEV_INLINE float tanh_fast(float x) { float y; asm("tanh.approx.f32 %0, %1;" : "=f"(y) : "f"(x)); return y; }
DEV_INLINE uint32_t smem_u32(const void* p) {
    uint32_t a;
    asm("{ .reg .u64 t; cvta.to.shared.u64 t, %1; cvt.u32.u64 %0, t; }" : "=r"(a) : "l"(p));
    return a;
}
DEV_INLINE void cp16(uint32_t dst, const void* src) {
    asm volatile("cp.async.cg.shared.global [%0], [%1], 16;" :: "r"(dst), "l"(src));
}

// ---- K0: zero accumulators ----
__global__ void k0_zero() {
    int i = blockIdx.x * 256 + threadIdx.x;
    if (i < B * PP) g_ssq[i] = 0.f;
    if (i < B * P)  g_ss[i]  = 0.f;
    if (i < B)      g_den[i] = 0.f;
    if (i < B * KK) { g_bcu[i] = 0.f; g_bsu[i] = 0.f; }
}

// ---- Kp: ws -> bf16 ----
__global__ void kprep(const float* __restrict__ ws) {
    int i = blockIdx.x * 256 + threadIdx.x;
    if (i >= KK * C / 4) return;
    float4 v = ((const float4*)ws)[i];
    ushort4 o;
    o.x = __bfloat16_as_ushort(__float2bfloat16_rn(v.x));
    o.y = __bfloat16_as_ushort(__float2bfloat16_rn(v.y));
    o.z = __bfloat16_as_ushort(__float2bfloat16_rn(v.z));
    o.w = __bfloat16_as_ushort(__float2bfloat16_rn(v.w));
    ((ushort4*)g_wsb)[i] = o;
}

// ---- K1: per-(b,c) sum & sumsq over P ----
__global__ void k1_stats(const float* __restrict__ x) {
    int warp = (blockIdx.x * blockDim.x + threadIdx.x) >> 5;
    int lane = threadIdx.x & 31;
    if (warp >= B * C) return;
    const float4* row = (const float4*)(x + (size_t)warp * P);
    float s = 0.f, sq = 0.f;
    for (int v = lane; v < 49; v += 32) {
        float4 f = row[v];
        s  += f.x + f.y + f.z + f.w;
        sq += f.x * f.x + f.y * f.y + f.z * f.z + f.w * f.w;
    }
    #pragma unroll
    for (int o = 16; o; o >>= 1) {
        s  += __shfl_down_sync(0xffffffffu, s,  o);
        sq += __shfl_down_sync(0xffffffffu, sq, o);
    }
    if (lane == 0) g_ic[warp] = s / (196.f * fmaxf(sqrtf(sq), 1e-12f));
}

// ---- K2: split-K tiled GEMM (R10 proven shape): bcu += whc@h, bsu += whs@h ----
__global__ void __launch_bounds__(256) k2_gemm(const float* __restrict__ h,
                                               const float* __restrict__ whc,
                                               const float* __restrict__ whs) {
    int jt = blockIdx.x, ks = blockIdx.y, mat = blockIdx.z;
    const float4* w4 = (const float4*)(mat ? whs : whc);
    const float4* h4 = (const float4*)h;
    float* outp = mat ? g_bsu : g_bcu;
    int j0 = jt * 32, kq0 = ks * 16;
    __shared__ float4 sh[64][17];
    __shared__ float4 sw[32][17];
    int tid = threadIdx.x;
    #pragma unroll
    for (int r = 0; r < 4; r++) {
        int idx = tid + 256 * r;
        sh[idx >> 4][idx & 15] = h4[(size_t)(idx >> 4) * 256 + kq0 + (idx & 15)];
    }
    #pragma unroll
    for (int r = 0; r < 2; r++) {
        int idx = tid + 256 * r;
        sw[idx >> 4][idx & 15] = w4[(size_t)(j0 + (idx >> 4)) * 256 + kq0 + (idx & 15)];
    }
    __syncthreads();
    int bq = tid & 15, jq = tid >> 4;
    float acc[2][4] = {{0.f,0.f,0.f,0.f},{0.f,0.f,0.f,0.f}};
    #pragma unroll
    for (int q = 0; q < 16; q++) {
        float4 w0 = sw[2 * jq][q], w1 = sw[2 * jq + 1][q];
        #pragma unroll
        for (int bb = 0; bb < 4; bb++) {
            float4 hv = sh[4 * bq + bb][q];
            acc[0][bb] = fmaf(w0.x, hv.x, fmaf(w0.y, hv.y, fmaf(w0.z, hv.z, fmaf(w0.w, hv.w, acc[0][bb]))));
            acc[1][bb] = fmaf(w1.x, hv.x, fmaf(w1.y, hv.y, fmaf(w1.z, hv.z, fmaf(w1.w, hv.w, acc[1][bb]))));
        }
    }
    #pragma unroll
    for (int jj = 0; jj < 2; jj++)
        #pragma unroll
        for (int bb = 0; bb < 4; bb++)
            atomicAdd(&outp[(4 * bq + bb) * KK + j0 + 2 * jq + jj], acc[jj][bb]);
}

// ---- K3: channel logits -> exp (no max shift; logits bounded), denom atomic ----
__global__ void k3_sc(const float* __restrict__ wc, const float* __restrict__ wci,
                      const float* __restrict__ bc) {
    int b = blockIdx.y;
    int c = blockIdx.x * 256 + threadIdx.x;
    int t = threadIdx.x;
    __shared__ float swc[KK], swi[KK], sbu[KK];
    __shared__ float red[256];
    for (int i = t; i < KK; i += 256) {
        swc[i] = wc[i]; swi[i] = wci[i]; sbu[i] = g_bcu[b * KK + i] + bc[i];
    }
    __syncthreads();
    float icv = g_ic[b * C + c], acc = 0.f;
    #pragma unroll 8
    for (int j = 0; j < KK; j++)
        acc = fmaf(swi[j], tanh_fast(fmaf(swc[j], icv, sbu[j])), acc);
    float e = __expf(acc);
    g_ac[b * C + c] = e;
    red[t] = e; __syncthreads();
    for (int o = 128; o; o >>= 1) { if (t < o) red[t] += red[t + o]; __syncthreads(); }
    if (t == 0) atomicAdd(&g_den[b], red[0]);
}

// ---- K5: xwb[b][p][c] = bf16(x * exp_ac/den); ssq via serial smem column sums ----
__global__ void __launch_bounds__(256) k5_xwT(const float* __restrict__ x) {
    int b = blockIdx.y, c0 = blockIdx.x * 32;
    __shared__ float t[32][201];
    int tid = threadIdx.x;
    float invden = __fdividef(1.f, g_den[b]);
    {
        int cc = tid >> 3, q0 = tid & 7;
        float a = g_ac[b * C + c0 + cc] * invden;
        const float4* src = (const float4*)(x + ((size_t)b * C + c0 + cc) * P);
        #pragma unroll
        for (int i = 0; i < 7; i++) {
            int q = q0 + 8 * i;
            if (q < 49) {
                float4 v = src[q];
                t[cc][4 * q + 0] = v.x * a;
                t[cc][4 * q + 1] = v.y * a;
                t[cc][4 * q + 2] = v.z * a;
                t[cc][4 * q + 3] = v.w * a;
            }
        }
    }
    __syncthreads();
    int lane = tid & 31, w = tid >> 5;
    for (int p = w; p < P; p += 8)
        g_xwb[((size_t)b * PP + p) * C + c0 + lane] = __float2bfloat16_rn(t[lane][p]);
    if (tid < P) {
        float s = 0.f;
        #pragma unroll
        for (int cc = 0; cc < 32; cc++) { float v = t[cc][tid]; s = fmaf(v, v, s); }
        atomicAdd(&g_ssq[b * PP + tid], s);
    }
}

// ============ K7: bf16 mma.sync m16n8k16, M128 x N224, K-chunks of 64 ============
constexpr int A_SZ  = 128 * 144;            // 18432
constexpr int STG   = A_SZ + 224 * 144;     // 50688
constexpr int SMEM_K7 = 2 * STG + 448 * 4;  // 103168

DEV_INLINE void mma16(float* c, const uint32_t* a, const uint32_t* bf) {
    asm volatile(
        "mma.sync.aligned.m16n8k16.row.col.f32.bf16.bf16.f32 "
        "{%0,%1,%2,%3}, {%4,%5,%6,%7}, {%8,%9}, {%0,%1,%2,%3};"
        : "+f"(c[0]), "+f"(c[1]), "+f"(c[2]), "+f"(c[3])
        : "r"(a[0]), "r"(a[1]), "r"(a[2]), "r"(a[3]), "r"(bf[0]), "r"(bf[1]));
}

__global__ void __launch_bounds__(256, 1) k7_mma(const float* __restrict__ wsi,
                                                 const float* __restrict__ bs) {
    extern __shared__ __align__(16) char sm[];
    const int tid = threadIdx.x;
    const int jbase = blockIdx.x * 128;
    const int b = blockIdx.y;
    const uint32_t sb = smem_u32(sm);

    const int wid = tid >> 5, lane = tid & 31;
    const int g = lane >> 2, t4 = lane & 3;
    const int m0 = (wid & 1) * 64;
    const int n0 = (wid >> 1) * 56;

    const size_t bbase = (size_t)b * PP;

    auto load_chunk = [&](int ch, int buf) {
        uint32_t abase = sb + buf * STG;
        uint32_t bbs   = abase + A_SZ;
        const __nv_bfloat16* asrc = g_wsb + ch * 64;
        const __nv_bfloat16* bsrc = g_xwb + bbase * 2048 + ch * 64;
        int idx = tid;
        #pragma unroll
        for (int r = 0; r < 4; r++, idx += 256) {
            int row = idx >> 3, q = idx & 7;
            cp16(abase + row * 144 + q * 16, asrc + (size_t)(jbase + row) * 2048 + q * 8);
        }
        idx = tid;
        #pragma unroll
        for (int r = 0; r < 7; r++, idx += 256) {
            int row = idx >> 3, q = idx & 7;
            cp16(bbs + row * 144 + q * 16, bsrc + (size_t)row * 2048 + q * 8);
        }
        asm volatile("cp.async.commit_group;");
    };

    float acc[4][7][4];
    #pragma unroll
    for (int mf = 0; mf < 4; mf++)
        #pragma unroll
        for (int nf = 0; nf < 7; nf++)
            #pragma unroll
            for (int i = 0; i < 4; i++) acc[mf][nf][i] = 0.f;

    load_chunk(0, 0);

    for (int ch = 0; ch < 32; ch++) {
        int buf = ch & 1;
        if (ch + 1 < 32) {
            load_chunk(ch + 1, buf ^ 1);
            asm volatile("cp.async.wait_group %0;" :: "n"(1));
        } else {
            asm volatile("cp.async.wait_group %0;" :: "n"(0));
        }
        __syncthreads();

        const char* aB = sm + buf * STG + (m0 + g) * 144 + t4 * 4;
        const char* bB = sm + buf * STG + A_SZ + (n0 + g) * 144 + t4 * 4;

        #pragma unroll
        for (int kk = 0; kk < 4; kk++) {
            const int ko = kk * 32;
            uint32_t a[4][4];
            #pragma unroll
            for (int mf = 0; mf < 4; mf++) {
                const char* ap = aB + mf * 16 * 144 + ko;
                a[mf][0] = *(const uint32_t*)(ap);
                a[mf][1] = *(const uint32_t*)(ap + 8 * 144);
                a[mf][2] = *(const uint32_t*)(ap + 16);
                a[mf][3] = *(const uint32_t*)(ap + 8 * 144 + 16);
            }
            uint32_t bf[7][2];
            #pragma unroll
            for (int nf = 0; nf < 7; nf++) {
                const char* bp = bB + nf * 8 * 144 + ko;
                bf[nf][0] = *(const uint32_t*)(bp);
                bf[nf][1] = *(const uint32_t*)(bp + 16);
            }
            #pragma unroll
            for (int mf = 0; mf < 4; mf++)
                #pragma unroll
                for (int nf = 0; nf < 7; nf++)
                    mma16(acc[mf][nf], a[mf], bf[nf]);
        }
        __syncthreads();
    }

    // ---- fused epilogue (inv norms inline from ssq) ----
    float* sinv  = (float*)(sm + 2 * STG);
    float* ssacc = sinv + 224;
    for (int i = tid; i < 224; i += 256) {
        sinv[i] = 1.f / fmaxf(sqrtf(g_ssq[bbase + i]), 1e-12f);
        ssacc[i] = 0.f;
    }
    __syncthreads();

    float invp[14];
    #pragma unroll
    for (int nf = 0; nf < 7; nf++) {
        invp[nf * 2 + 0] = sinv[n0 + nf * 8 + 2 * t4 + 0];
        invp[nf * 2 + 1] = sinv[n0 + nf * 8 + 2 * t4 + 1];
    }
    float psum[14];
    #pragma unroll
    for (int i = 0; i < 14; i++) psum[i] = 0.f;

    #pragma unroll
    for (int mf = 0; mf < 4; mf++) {
        #pragma unroll
        for (int rr = 0; rr < 2; rr++) {
            int j = jbase + m0 + mf * 16 + rr * 8 + g;
            float bj = g_bsu[b * KK + j] + bs[j];
            float wj = wsi[j];
            #pragma unroll
            for (int nf = 0; nf < 7; nf++) {
                #pragma unroll
                for (int cc = 0; cc < 2; cc++) {
                    float d = acc[mf][nf][rr * 2 + cc];
                    psum[nf * 2 + cc] = fmaf(wj, tanh_fast(fmaf(d, invp[nf * 2 + cc], bj)),
                                             psum[nf * 2 + cc]);
                }
            }
        }
    }
    #pragma unroll
    for (int nf = 0; nf < 7; nf++)
        #pragma unroll
        for (int cc = 0; cc < 2; cc++) {
            int p = n0 + nf * 8 + 2 * t4 + cc;
            if (p < P) atomicAdd(&ssacc[p], psum[nf * 2 + cc]);
        }
    __syncthreads();
    if (tid < P) atomicAdd(&g_ss[b * P + tid], ssacc[tid]);
}

// ---- K8: softmax over P ----
__global__ void k8_softmax_p() {
    int b = blockIdx.x, t = threadIdx.x;
    __shared__ float red[256];
    float v = (t < P) ? g_ss[b * P + t] : -1e30f;
    red[t] = v; __syncthreads();
    for (int o = 128; o; o >>= 1) { if (t < o) red[t] = fmaxf(red[t], red[t + o]); __syncthreads(); }
    float m = red[0]; __syncthreads();
    float e = (t < P) ? __expf(v - m) : 0.f;
    red[t] = e; __syncthreads();
    for (int o = 128; o; o >>= 1) { if (t < o) red[t] += red[t + o]; __syncthreads(); }
    if (t < P) g_asp[b * P + t] = e / red[0];
}

// ---- K9: out = img * (exp_ac/den) * asp ----
__global__ void k9_out(const float* __restrict__ x, float* __restrict__ out) {
    int idx = blockIdx.x * 256 + threadIdx.x;
    if (idx >= B * C * 49) return;
    int q = idx % 49;
    int bc = idx / 49;
    int b = bc >> 11;
    float a = g_ac[bc] * __fdividef(1.f, g_den[b]);
    float4 v = ((const float4*)x)[idx];
    float4 s = ((const float4*)g_asp)[b * 49 + q];
    float4 o;
    o.x = v.x * a * s.x; o.y = v.y * a * s.y; o.z = v.z * a * s.z; o.w = v.w * a * s.w;
    ((float4*)out)[idx] = o;
}

extern "C" void kernel_launch(void* const* d_in, const int* in_sizes, int n_in,
                              void* d_out, int out_size) {
    const float* img = (const float*)d_in[0];
    const float* h   = (const float*)d_in[1];
    const float* wc  = (const float*)d_in[2];
    const float* bc  = (const float*)d_in[3];
    const float* whc = (const float*)d_in[4];
    const float* wci = (const float*)d_in[5];
    const float* ws  = (const float*)d_in[7];
    const float* bs  = (const float*)d_in[8];
    const float* whs = (const float*)d_in[9];
    const float* wsi = (const float*)d_in[10];
    float* out = (float*)d_out;

    cudaFuncSetAttribute(k7_mma, cudaFuncAttributeMaxDynamicSharedMemorySize, SMEM_K7);

    k0_zero<<<(B * KK + 255) / 256, 256>>>();
    kprep<<<(KK * C / 4 + 255) / 256, 256>>>(ws);
    k1_stats<<<(B * C) / 8, 256>>>(img);
    k2_gemm<<<dim3(16, 16, 2), 256>>>(h, whc, whs);
    k3_sc<<<dim3(C / 256, B), 256>>>(wc, wci, bc);
    k5_xwT<<<dim3(C / 32, B), 256>>>(img);
    k7_mma<<<dim3(4, B), 256, SMEM_K7>>>(wsi, bs);
    k8_softmax_p<<<B, 256>>>();
    k9_out<<<(B * C * 49 + 255) / 256, 256>>>(img, out);
}